// round 15
// baseline (speedup 1.0000x reference)
#include <cuda_runtime.h>
#include <cuda_bf16.h>
#include <math.h>
#include <stdint.h>

#define THR 128

// ---- smem byte offsets (per CTA, 93.7KB -> 2 CTAs/SM) ----
#define OFF_SCR   0        // 256 floats
#define OFF_BR    1024
#define OFF_BZ    1536
#define OFF_BIN   2048
#define OFF_BHN   2560
#define OFF_MSGB  3072
#define OFF_ATT   3584     // attn 64 x 72 bf16 hi (9216B), lo +9216  -> ends 22016
#define OFF_INT   22016    // overlay: SWT 128x72 (hi, lo +18432) / AM 64x136 (hi, lo +17408) -> ends 58880
#define OFF_S     58880    // S 64x136 bf16 hi (17408), lo +17408 -> ends 93696
#define SMEM_TOTAL 93696

#define STB_X  272     // byte stride for 128-col arrays (136 bf16)
#define STB_W  144     // byte stride for 64-col arrays  (72 bf16)
#define HL_X   17408
#define HL_ATT 9216
#define HL_SWT 18432

// weights in A-fragment-native layout: index ((tile*64 + mt*8 + kt)*32 + lane)
// tile: 0 = w^T, 1..3 = W_ih r/z/n, 4..6 = W_hh r/z/n
__device__ __align__(16) uint4 g_wf_hi[7 * 64 * 32];
__device__ __align__(16) uint4 g_wf_lo[7 * 64 * 32];

__device__ __forceinline__ float wfetch(int tile, int g, int k,
                                        const float* w, const float* W_ih,
                                        const float* W_hh) {
    if (tile == 0) return w[k * 128 + g];                    // w^T[d][k]
    if (tile <= 3) return W_ih[((tile - 1) * 128 + g) * 128 + k];
    return W_hh[((tile - 4) * 128 + g) * 128 + k];
}

__global__ void prep_weights(const float* __restrict__ w,
                             const float* __restrict__ W_ih,
                             const float* __restrict__ W_hh) {
    int idx = blockIdx.x * blockDim.x + threadIdx.x;
    if (idx >= 7 * 64 * 32) return;
    int lane = idx & 31, kt = (idx >> 5) & 7, mt = (idx >> 8) & 7, tile = idx >> 11;
    int g = mt * 16 + (lane >> 2), k = kt * 16 + (lane & 3) * 2;
    const int dr[4] = {0, 8, 0, 8};
    const int dc[4] = {0, 0, 8, 8};
    uint32_t hi[4], lo[4];
#pragma unroll
    for (int a = 0; a < 4; a++) {
        float v0 = wfetch(tile, g + dr[a], k + dc[a], w, W_ih, W_hh);
        float v1 = wfetch(tile, g + dr[a], k + dc[a] + 1, w, W_ih, W_hh);
        __nv_bfloat16 h0 = __float2bfloat16(v0);
        __nv_bfloat16 l0 = __float2bfloat16(v0 - __bfloat162float(h0));
        __nv_bfloat16 h1 = __float2bfloat16(v1);
        __nv_bfloat16 l1 = __float2bfloat16(v1 - __bfloat162float(h1));
        __nv_bfloat162 ph(h0, h1), pl(l0, l1);
        hi[a] = *reinterpret_cast<uint32_t*>(&ph);
        lo[a] = *reinterpret_cast<uint32_t*>(&pl);
    }
    g_wf_hi[idx] = make_uint4(hi[0], hi[1], hi[2], hi[3]);
    g_wf_lo[idx] = make_uint4(lo[0], lo[1], lo[2], lo[3]);
}

// ---- device helpers ----
__device__ __forceinline__ uint32_t smem_u32(const void* p) {
    uint32_t a;
    asm("{ .reg .u64 t; cvta.to.shared.u64 t, %1; cvt.u32.u64 %0, t; }" : "=r"(a) : "l"(p));
    return a;
}
__device__ __forceinline__ void ldsm4(uint32_t* r, uint32_t a) {
    asm volatile("ldmatrix.sync.aligned.m8n8.x4.shared.b16 {%0,%1,%2,%3}, [%4];"
                 : "=r"(r[0]), "=r"(r[1]), "=r"(r[2]), "=r"(r[3]) : "r"(a));
}
__device__ __forceinline__ void mma_bf16(float* c, const uint32_t* a,
                                         uint32_t b0, uint32_t b1) {
    asm volatile("mma.sync.aligned.m16n8k16.row.col.f32.bf16.bf16.f32 "
                 "{%0,%1,%2,%3}, {%4,%5,%6,%7}, {%8,%9}, {%0,%1,%2,%3};"
                 : "+f"(c[0]), "+f"(c[1]), "+f"(c[2]), "+f"(c[3])
                 : "r"(a[0]), "r"(a[1]), "r"(a[2]), "r"(a[3]), "r"(b0), "r"(b1));
}
__device__ __forceinline__ float rbf(const char* p) {
    return __bfloat162float(*reinterpret_cast<const __nv_bfloat16*>(p));
}
__device__ __forceinline__ void st_split_pair(char* hi, char* lo, float v0, float v1) {
    __nv_bfloat16 h0 = __float2bfloat16(v0);
    __nv_bfloat16 l0 = __float2bfloat16(v0 - __bfloat162float(h0));
    __nv_bfloat16 h1 = __float2bfloat16(v1);
    __nv_bfloat16 l1 = __float2bfloat16(v1 - __bfloat162float(h1));
    __nv_bfloat162 ph(h0, h1), pl(l0, l1);
    *reinterpret_cast<uint32_t*>(hi) = *reinterpret_cast<uint32_t*>(&ph);
    *reinterpret_cast<uint32_t*>(lo) = *reinterpret_cast<uint32_t*>(&pl);
}
__device__ __forceinline__ float sigmoidf_(float x) { return 1.f / (1.f + __expf(-x)); }

__global__ __launch_bounds__(THR, 2)
void fignn_mma(const float* __restrict__ h_g,
               const float* __restrict__ a_src, const float* __restrict__ a_dst,
               const float* __restrict__ bias_g,
               const float* __restrict__ b_ih, const float* __restrict__ b_hh,
               const float* __restrict__ mlp1_w, const float* __restrict__ mlp1_b,
               const float* __restrict__ mlp2_w, const float* __restrict__ mlp2_b,
               const int* __restrict__ steps_p, float* __restrict__ out) {
    extern __shared__ char smem[];
    const uint32_t sb = smem_u32(smem);
    const int tid = threadIdx.x, lane = tid & 31, wid = tid >> 5;   // 4 warps
    const int b = blockIdx.x;
    const float* hb = h_g + (size_t)b * 64 * 128;

    float* scr  = reinterpret_cast<float*>(smem + OFF_SCR);
    float* vbr  = reinterpret_cast<float*>(smem + OFF_BR);
    float* vbz  = reinterpret_cast<float*>(smem + OFF_BZ);
    float* vbin = reinterpret_cast<float*>(smem + OFF_BIN);
    float* vbhn = reinterpret_cast<float*>(smem + OFF_BHN);
    float* msgb = reinterpret_cast<float*>(smem + OFF_MSGB);

    // ---- init: split h -> S (no fp32 H mirror; residual re-read from global) ----
    for (int t = tid; t < 2048; t += THR) {
        float4 v = reinterpret_cast<const float4*>(hb)[t];
        int i = t >> 5, k0 = (t & 31) * 4;
        char* p = smem + OFF_S + i * STB_X + k0 * 2;
        st_split_pair(p, p + HL_X, v.x, v.y);
        st_split_pair(p + 4, p + 4 + HL_X, v.z, v.w);
    }
    if (tid < 128) {
        vbr[tid]  = b_ih[tid] + b_hh[tid];
        vbz[tid]  = b_ih[128 + tid] + b_hh[128 + tid];
        vbin[tid] = b_ih[256 + tid];
        vbhn[tid] = b_hh[256 + tid];
        msgb[tid] = bias_g[tid];
    }
    // attention dots
    for (int idx = wid; idx < 128; idx += 4) {
        int i = idx & 63;
        const float* vec = (idx < 64) ? a_src : a_dst;
        float acc = 0.f;
#pragma unroll
        for (int m = 0; m < 4; m++)
            acc += hb[i * 128 + lane + m * 32] * vec[lane + m * 32];
#pragma unroll
        for (int o = 16; o > 0; o >>= 1) acc += __shfl_xor_sync(0xffffffffu, acc, o);
        if (lane == 0) scr[idx] = acc;
    }
    __syncthreads();
    // softmax rows -> ATT bf16 split
    for (int row = wid; row < 64; row += 4) {
        float srci = scr[row];
        int j0 = lane, j1 = lane + 32;
        float v0 = srci + scr[64 + j0], v1 = srci + scr[64 + j1];
        v0 = v0 > 0.f ? v0 : 0.2f * v0;
        v1 = v1 > 0.f ? v1 : 0.2f * v1;
        if (j0 == row) v0 = 0.f;
        if (j1 == row) v1 = 0.f;
        float m = fmaxf(v0, v1);
#pragma unroll
        for (int o = 16; o > 0; o >>= 1) m = fmaxf(m, __shfl_xor_sync(0xffffffffu, m, o));
        float e0 = __expf(v0 - m), e1 = __expf(v1 - m);
        float s2 = e0 + e1;
#pragma unroll
        for (int o = 16; o > 0; o >>= 1) s2 += __shfl_xor_sync(0xffffffffu, s2, o);
        float inv = 1.f / s2;
        char* p0 = smem + OFF_ATT + row * STB_W + j0 * 2;
        char* p1 = smem + OFF_ATT + row * STB_W + j1 * 2;
        float a0 = e0 * inv, a1 = e1 * inv;
        __nv_bfloat16 hh = __float2bfloat16(a0);
        *reinterpret_cast<__nv_bfloat16*>(p0) = hh;
        *reinterpret_cast<__nv_bfloat16*>(p0 + HL_ATT) =
            __float2bfloat16(a0 - __bfloat162float(hh));
        hh = __float2bfloat16(a1);
        *reinterpret_cast<__nv_bfloat16*>(p1) = hh;
        *reinterpret_cast<__nv_bfloat16*>(p1 + HL_ATT) =
            __float2bfloat16(a1 - __bfloat162float(hh));
    }
    __syncthreads();

    // per-lane fragment offsets
    const int rB = (lane & 7) + ((lane >> 4) << 3);
    const int cB = ((lane >> 3) & 1) * 8;
    const int rA = (lane & 7) + ((lane >> 3) & 1) * 8;
    const int cA = ((lane >> 4) & 1) * 8;
    const uint32_t bOffX = rB * STB_X + cB * 2;
    const uint32_t bOffW = rB * STB_W + cB * 2;
    const uint32_t aOffW = rA * STB_W + cA * 2;
    const int r_ = lane >> 2, c2 = (lane & 3) * 2;

    const int steps = steps_p ? steps_p[0] : 3;

    for (int it = 0; it < steps; it++) {
        // ===== G1: SWT[d][j] = sum_k wT[d][k]*S[j][k]  (M=128,N=64,K=128) =====
        // warp does 2 sequential 16-row m-tiles (mt = wid*2+msub); acc 32 floats
#pragma unroll 1
        for (int msub = 0; msub < 2; msub++) {
            const int mt = wid * 2 + msub;
            float acc[8][4];
#pragma unroll
            for (int a = 0; a < 8; a++)
#pragma unroll
                for (int e = 0; e < 4; e++) acc[a][e] = 0.f;
            for (int t3 = 0; t3 < 3; t3++) {
                const uint4* wb = (t3 == 2) ? g_wf_lo : g_wf_hi;
                uint32_t Bb = sb + OFF_S + ((t3 == 1) ? HL_X : 0) + bOffX;
#pragma unroll
                for (int kt = 0; kt < 8; kt++) {
                    uint4 af = wb[((mt * 8 + kt) << 5) + lane];
#pragma unroll
                    for (int n2 = 0; n2 < 4; n2++) {
                        uint32_t bf[4];
                        ldsm4(bf, Bb + n2 * 16 * STB_X + kt * 32);
                        mma_bf16(acc[n2 * 2], reinterpret_cast<uint32_t*>(&af), bf[0], bf[1]);
                        mma_bf16(acc[n2 * 2 + 1], reinterpret_cast<uint32_t*>(&af), bf[2], bf[3]);
                    }
                }
            }
#pragma unroll
            for (int nt = 0; nt < 8; nt++) {
                int d0 = mt * 16 + r_, j = nt * 8 + c2;
                char* p = smem + OFF_INT + d0 * STB_W + j * 2;
                st_split_pair(p, p + HL_SWT, acc[nt][0], acc[nt][1]);
                p += 8 * STB_W;
                st_split_pair(p, p + HL_SWT, acc[nt][2], acc[nt][3]);
            }
        }
        __syncthreads();
        // ===== G2: AM[i][d] = sum_j attn[i][j]*SWT[d][j] + msgb  (M=64,N=128,K=64)
        //       Full result held in regs (64 f); AM overlays SWT after barrier. =====
        {
            const int i0 = wid * 16;
            float acc[16][4];
#pragma unroll
            for (int a = 0; a < 16; a++)
#pragma unroll
                for (int e = 0; e < 4; e++) acc[a][e] = 0.f;
            for (int t3 = 0; t3 < 3; t3++) {
                uint32_t Ab = sb + OFF_ATT + ((t3 == 2) ? HL_ATT : 0) + aOffW + i0 * STB_W;
                uint32_t Bb = sb + OFF_INT + ((t3 == 1) ? HL_SWT : 0) + bOffW;
#pragma unroll
                for (int kt = 0; kt < 4; kt++) {
                    uint32_t af[4];
                    ldsm4(af, Ab + kt * 32);
#pragma unroll
                    for (int n2 = 0; n2 < 8; n2++) {
                        uint32_t bf[4];
                        ldsm4(bf, Bb + n2 * 16 * STB_W + kt * 32);
                        mma_bf16(acc[n2 * 2], af, bf[0], bf[1]);
                        mma_bf16(acc[n2 * 2 + 1], af, bf[2], bf[3]);
                    }
                }
            }
            __syncthreads();   // all SWT reads complete -> safe to overlay AM
#pragma unroll
            for (int nt = 0; nt < 16; nt++) {
                int d = nt * 8 + c2;
                float m0 = msgb[d], m1 = msgb[d + 1];
                char* p = smem + OFF_INT + (i0 + r_) * STB_X + d * 2;
                st_split_pair(p, p + HL_X, acc[nt][0] + m0, acc[nt][1] + m1);
                p += 8 * STB_X;
                st_split_pair(p, p + HL_X, acc[nt][2] + m0, acc[nt][3] + m1);
            }
        }
        __syncthreads();
        // ===== gates: D[g][i]; warp owns g-range 32 (m=2), loops 4 i-chunks of 16.
        //       B ldsm shared across 3 gates x 2 m per kt. In-place S update
        //       guarded by per-chunk barrier. =====
#pragma unroll 1
        for (int ic = 0; ic < 4; ic++) {
            float acc[4][2][2][4];   // set x m x n x 4 == 64 floats
#pragma unroll
            for (int s = 0; s < 4; s++)
#pragma unroll
                for (int m = 0; m < 2; m++)
#pragma unroll
                    for (int n = 0; n < 2; n++)
#pragma unroll
                        for (int e = 0; e < 4; e++) acc[s][m][n][e] = 0.f;
#pragma unroll
            for (int src = 0; src < 2; src++) {
                const uint32_t Bbase = (src == 0) ? (uint32_t)OFF_INT : (uint32_t)OFF_S;
                for (int t3 = 0; t3 < 3; t3++) {
                    const uint4* wb = (t3 == 2) ? g_wf_lo : g_wf_hi;
                    uint32_t Bb = sb + Bbase + ((t3 == 1) ? HL_X : 0) + bOffX +
                                  ic * 16 * STB_X;
#pragma unroll
                    for (int kt = 0; kt < 8; kt++) {
                        uint32_t bf[4];
                        ldsm4(bf, Bb + kt * 32);
#pragma unroll
                        for (int gate = 0; gate < 3; gate++) {
                            const int set = (gate < 2) ? gate : (2 + src);
                            const int tile = 1 + gate + 3 * src;
#pragma unroll
                            for (int m = 0; m < 2; m++) {
                                uint4 af = wb[((tile * 64 + (wid * 2 + m) * 8 + kt) << 5) + lane];
                                mma_bf16(acc[set][m][0],
                                         reinterpret_cast<uint32_t*>(&af), bf[0], bf[1]);
                                mma_bf16(acc[set][m][1],
                                         reinterpret_cast<uint32_t*>(&af), bf[2], bf[3]);
                            }
                        }
                    }
                }
            }
            __syncthreads();   // all warps done reading S[ic]/AM[ic]
            // GRU pointwise for 32g x 16i; in-place S write (rows ic only)
#pragma unroll
            for (int m = 0; m < 2; m++) {
#pragma unroll
                for (int q = 0; q < 2; q++) {
                    int g = wid * 32 + m * 16 + r_ + q * 8;
                    float bR = vbr[g], bZ = vbz[g], bI = vbin[g], bH = vbhn[g];
#pragma unroll
                    for (int n = 0; n < 2; n++) {
#pragma unroll
                        for (int e = 0; e < 2; e++) {
                            int i = ic * 16 + n * 8 + c2 + e;
                            int ci = q * 2 + e;
                            float R  = sigmoidf_(acc[0][m][n][ci] + bR);
                            float Z  = sigmoidf_(acc[1][m][n][ci] + bZ);
                            float Nv = tanhf(acc[2][m][n][ci] + bI +
                                             R * (acc[3][m][n][ci] + bH));
                            char* sp = smem + OFF_S + i * STB_X + g * 2;
                            float sold = rbf(sp) + rbf(sp + HL_X);
                            float hres = __ldg(hb + i * 128 + g);
                            float sv = (1.f - Z) * Nv + Z * sold + hres;
                            __nv_bfloat16 hh = __float2bfloat16(sv);
                            *reinterpret_cast<__nv_bfloat16*>(sp) = hh;
                            *reinterpret_cast<__nv_bfloat16*>(sp + HL_X) =
                                __float2bfloat16(sv - __bfloat162float(hh));
                        }
                    }
                }
            }
        }
        __syncthreads();   // step end: S fully updated before next G1 / readout
    }

    // ===== readout =====
    if (tid < 64) {
        float acc = 0.f;
#pragma unroll 8
        for (int k = 0; k < 128; k++) {
            char* sp = smem + OFF_S + tid * STB_X + k * 2;
            acc += (rbf(sp) + rbf(sp + HL_X)) * mlp2_w[k];
        }
        scr[tid] = acc + mlp2_b[0];
    }
    __syncthreads();
    if (tid < 128) {
        float acc = 0.f;
#pragma unroll 4
        for (int n = 0; n < 64; n++) {
            char* sp = smem + OFF_S + n * STB_X + tid * 2;
            acc += scr[n] * (rbf(sp) + rbf(sp + HL_X));
        }
        scr[64 + tid] = acc;
    }
    __syncthreads();
    if (tid < 64) {
        float acc = 0.f;
#pragma unroll 4
        for (int d = 0; d < 128; d++) acc += scr[64 + d] * mlp1_w[d * 64 + tid];
        float ws = 0.f;
#pragma unroll
        for (int n = 0; n < 64; n++) ws += scr[n];
        out[(size_t)b * 64 + tid] = acc + ws * mlp1_b[tid];
    }
}

extern "C" void kernel_launch(void* const* d_in, const int* in_sizes, int n_in,
                              void* d_out, int out_size) {
    const float* h      = (const float*)d_in[0];
    // d_in[1] = adj: unused by the math (shape only)
    const float* a_src  = (const float*)d_in[2];
    const float* a_dst  = (const float*)d_in[3];
    const float* w      = (const float*)d_in[4];
    const float* bias   = (const float*)d_in[5];
    const float* W_ih   = (const float*)d_in[6];
    const float* W_hh   = (const float*)d_in[7];
    const float* b_ih   = (const float*)d_in[8];
    const float* b_hh   = (const float*)d_in[9];
    const float* mlp1_w = (const float*)d_in[10];
    const float* mlp1_b = (const float*)d_in[11];
    const float* mlp2_w = (const float*)d_in[12];
    const float* mlp2_b = (const float*)d_in[13];
    const int*   steps  = (n_in > 14) ? (const int*)d_in[14] : nullptr;

    int batches = in_sizes[0] / (64 * 128);

    cudaFuncSetAttribute(fignn_mma, cudaFuncAttributeMaxDynamicSharedMemorySize,
                         SMEM_TOTAL);
    prep_weights<<<(7 * 64 * 32 + 255) / 256, 256>>>(w, W_ih, W_hh);
    fignn_mma<<<batches, THR, SMEM_TOTAL>>>(h, a_src, a_dst, bias, b_ih, b_hh,
                                            mlp1_w, mlp1_b, mlp2_w, mlp2_b,
                                            steps, (float*)d_out);
}

// round 16
// speedup vs baseline: 1.0946x; 1.0946x over previous
#include <cuda_runtime.h>
#include <cuda_bf16.h>
#include <math.h>
#include <stdint.h>

#define THR 384
#define NW  12

// ---- smem byte offsets (1 CTA/SM, 196KB) ----
#define OFF_SCR   0        // 256 floats scratch
#define OFF_BR    1024     // 128 f32
#define OFF_BZ    1536
#define OFF_BIN   2048
#define OFF_BHN   2560
#define OFF_MSGB  3072     // 128 f32
#define OFF_ATT   3584     // attn: 64 x 72 bf16 hi (9216B), lo +9216
#define OFF_SWT   22016    // SW^T: 128 x 72 bf16 hi (18432B), lo +18432
#define OFF_S     58880    // S buf A: 64 x 136 bf16 hi (17408B), lo +17408
#define OFF_AM    93696    // Amsg: 64 x 136 bf16 hi, lo +17408
#define OFF_H     128512   // h residual fp32 64x128 (32768B)
#define OFF_S2    161280   // S buf B
#define SMEM_TOTAL 196096

#define STB_X  272     // byte stride for 128-col arrays (136 bf16)
#define STB_W  144     // byte stride for 64-col arrays  (72 bf16)
#define HL_X   17408
#define HL_ATT 9216
#define HL_SWT 18432

// weights in A-fragment-native layout: index ((tile*64 + mt*8 + kt)*32 + lane)
// tile: 0 = w^T, 1..3 = W_ih r/z/n, 4..6 = W_hh r/z/n
__device__ __align__(16) uint4 g_wf_hi[7 * 64 * 32];
__device__ __align__(16) uint4 g_wf_lo[7 * 64 * 32];

__device__ __forceinline__ float wfetch(int tile, int g, int k,
                                        const float* w, const float* W_ih,
                                        const float* W_hh) {
    if (tile == 0) return w[k * 128 + g];                    // w^T[d][k]
    if (tile <= 3) return W_ih[((tile - 1) * 128 + g) * 128 + k];
    return W_hh[((tile - 4) * 128 + g) * 128 + k];
}

__global__ void prep_weights(const float* __restrict__ w,
                             const float* __restrict__ W_ih,
                             const float* __restrict__ W_hh) {
    int idx = blockIdx.x * blockDim.x + threadIdx.x;
    if (idx >= 7 * 64 * 32) return;
    int lane = idx & 31, kt = (idx >> 5) & 7, mt = (idx >> 8) & 7, tile = idx >> 11;
    int g = mt * 16 + (lane >> 2), k = kt * 16 + (lane & 3) * 2;
    const int dr[4] = {0, 8, 0, 8};
    const int dc[4] = {0, 0, 8, 8};
    uint32_t hi[4], lo[4];
#pragma unroll
    for (int a = 0; a < 4; a++) {
        float v0 = wfetch(tile, g + dr[a], k + dc[a], w, W_ih, W_hh);
        float v1 = wfetch(tile, g + dr[a], k + dc[a] + 1, w, W_ih, W_hh);
        __nv_bfloat16 h0 = __float2bfloat16(v0);
        __nv_bfloat16 l0 = __float2bfloat16(v0 - __bfloat162float(h0));
        __nv_bfloat16 h1 = __float2bfloat16(v1);
        __nv_bfloat16 l1 = __float2bfloat16(v1 - __bfloat162float(h1));
        __nv_bfloat162 ph(h0, h1), pl(l0, l1);
        hi[a] = *reinterpret_cast<uint32_t*>(&ph);
        lo[a] = *reinterpret_cast<uint32_t*>(&pl);
    }
    g_wf_hi[idx] = make_uint4(hi[0], hi[1], hi[2], hi[3]);
    g_wf_lo[idx] = make_uint4(lo[0], lo[1], lo[2], lo[3]);
}

// ---- device helpers ----
__device__ __forceinline__ uint32_t smem_u32(const void* p) {
    uint32_t a;
    asm("{ .reg .u64 t; cvta.to.shared.u64 t, %1; cvt.u32.u64 %0, t; }" : "=r"(a) : "l"(p));
    return a;
}
__device__ __forceinline__ void ldsm4(uint32_t* r, uint32_t a) {
    asm volatile("ldmatrix.sync.aligned.m8n8.x4.shared.b16 {%0,%1,%2,%3}, [%4];"
                 : "=r"(r[0]), "=r"(r[1]), "=r"(r[2]), "=r"(r[3]) : "r"(a));
}
__device__ __forceinline__ void mma_bf16(float* c, const uint32_t* a,
                                         uint32_t b0, uint32_t b1) {
    asm volatile("mma.sync.aligned.m16n8k16.row.col.f32.bf16.bf16.f32 "
                 "{%0,%1,%2,%3}, {%4,%5,%6,%7}, {%8,%9}, {%0,%1,%2,%3};"
                 : "+f"(c[0]), "+f"(c[1]), "+f"(c[2]), "+f"(c[3])
                 : "r"(a[0]), "r"(a[1]), "r"(a[2]), "r"(a[3]), "r"(b0), "r"(b1));
}
__device__ __forceinline__ float rbf(const char* p) {
    return __bfloat162float(*reinterpret_cast<const __nv_bfloat16*>(p));
}
__device__ __forceinline__ void st_split_pair(char* hi, char* lo, float v0, float v1) {
    __nv_bfloat16 h0 = __float2bfloat16(v0);
    __nv_bfloat16 l0 = __float2bfloat16(v0 - __bfloat162float(h0));
    __nv_bfloat16 h1 = __float2bfloat16(v1);
    __nv_bfloat16 l1 = __float2bfloat16(v1 - __bfloat162float(h1));
    __nv_bfloat162 ph(h0, h1), pl(l0, l1);
    *reinterpret_cast<uint32_t*>(hi) = *reinterpret_cast<uint32_t*>(&ph);
    *reinterpret_cast<uint32_t*>(lo) = *reinterpret_cast<uint32_t*>(&pl);
}
__device__ __forceinline__ float sigmoidf_(float x) { return 1.f / (1.f + __expf(-x)); }

__global__ __launch_bounds__(THR, 1)
void fignn_mma(const float* __restrict__ h_g,
               const float* __restrict__ a_src, const float* __restrict__ a_dst,
               const float* __restrict__ bias_g,
               const float* __restrict__ b_ih, const float* __restrict__ b_hh,
               const float* __restrict__ mlp1_w, const float* __restrict__ mlp1_b,
               const float* __restrict__ mlp2_w, const float* __restrict__ mlp2_b,
               const int* __restrict__ steps_p, float* __restrict__ out) {
    extern __shared__ char smem[];
    const uint32_t sb = smem_u32(smem);
    const int tid = threadIdx.x, lane = tid & 31, wid = tid >> 5;   // 12 warps
    const int b = blockIdx.x;
    const float* hb = h_g + (size_t)b * 64 * 128;

    float* scr  = reinterpret_cast<float*>(smem + OFF_SCR);
    float* vbr  = reinterpret_cast<float*>(smem + OFF_BR);
    float* vbz  = reinterpret_cast<float*>(smem + OFF_BZ);
    float* vbin = reinterpret_cast<float*>(smem + OFF_BIN);
    float* vbhn = reinterpret_cast<float*>(smem + OFF_BHN);
    float* msgb = reinterpret_cast<float*>(smem + OFF_MSGB);

    // ---- init: h -> H fp32 + S bf16 split (buf A) ----
    for (int t = tid; t < 2048; t += THR) {
        float4 v = reinterpret_cast<const float4*>(hb)[t];
        int i = t >> 5, k0 = (t & 31) * 4;
        *reinterpret_cast<float4*>(smem + OFF_H + (i * 128 + k0) * 4) = v;
        char* p = smem + OFF_S + i * STB_X + k0 * 2;
        st_split_pair(p, p + HL_X, v.x, v.y);
        st_split_pair(p + 4, p + 4 + HL_X, v.z, v.w);
    }
    if (tid < 128) {
        vbr[tid]  = b_ih[tid] + b_hh[tid];
        vbz[tid]  = b_ih[128 + tid] + b_hh[128 + tid];
        vbin[tid] = b_ih[256 + tid];
        vbhn[tid] = b_hh[256 + tid];
        msgb[tid] = bias_g[tid];
    }
    // attention dots
    for (int idx = wid; idx < 128; idx += NW) {
        int i = idx & 63;
        const float* vec = (idx < 64) ? a_src : a_dst;
        float acc = 0.f;
#pragma unroll
        for (int m = 0; m < 4; m++)
            acc += hb[i * 128 + lane + m * 32] * vec[lane + m * 32];
#pragma unroll
        for (int o = 16; o > 0; o >>= 1) acc += __shfl_xor_sync(0xffffffffu, acc, o);
        if (lane == 0) scr[idx] = acc;
    }
    __syncthreads();
    // softmax rows -> ATT bf16 split
    for (int row = wid; row < 64; row += NW) {
        float srci = scr[row];
        int j0 = lane, j1 = lane + 32;
        float v0 = srci + scr[64 + j0], v1 = srci + scr[64 + j1];
        v0 = v0 > 0.f ? v0 : 0.2f * v0;
        v1 = v1 > 0.f ? v1 : 0.2f * v1;
        if (j0 == row) v0 = 0.f;
        if (j1 == row) v1 = 0.f;
        float m = fmaxf(v0, v1);
#pragma unroll
        for (int o = 16; o > 0; o >>= 1) m = fmaxf(m, __shfl_xor_sync(0xffffffffu, m, o));
        float e0 = __expf(v0 - m), e1 = __expf(v1 - m);
        float s2 = e0 + e1;
#pragma unroll
        for (int o = 16; o > 0; o >>= 1) s2 += __shfl_xor_sync(0xffffffffu, s2, o);
        float inv = 1.f / s2;
        char* p0 = smem + OFF_ATT + row * STB_W + j0 * 2;
        char* p1 = smem + OFF_ATT + row * STB_W + j1 * 2;
        float a0 = e0 * inv, a1 = e1 * inv;
        __nv_bfloat16 hh = __float2bfloat16(a0);
        *reinterpret_cast<__nv_bfloat16*>(p0) = hh;
        *reinterpret_cast<__nv_bfloat16*>(p0 + HL_ATT) =
            __float2bfloat16(a0 - __bfloat162float(hh));
        hh = __float2bfloat16(a1);
        *reinterpret_cast<__nv_bfloat16*>(p1) = hh;
        *reinterpret_cast<__nv_bfloat16*>(p1 + HL_ATT) =
            __float2bfloat16(a1 - __bfloat162float(hh));
    }
    __syncthreads();

    // per-lane fragment offsets
    const int rB = (lane & 7) + ((lane >> 4) << 3);
    const int cB = ((lane >> 3) & 1) * 8;
    const int rA = (lane & 7) + ((lane >> 3) & 1) * 8;
    const int cA = ((lane >> 4) & 1) * 8;
    const uint32_t bOffX = rB * STB_X + cB * 2;
    const uint32_t bOffW = rB * STB_W + cB * 2;
    const uint32_t aOffW = rA * STB_W + cA * 2;
    const int r_ = lane >> 2, c2 = (lane & 3) * 2;

    const int steps = steps_p ? steps_p[0] : 3;
    uint32_t cur = OFF_S, nxt = OFF_S2;

    for (int it = 0; it < steps; it++) {
        // ===== G1: SWT[d][j] = sum_k wT[d][k]*S[j][k]  (M=128,N=64,K=128)
        //       32 tiles of 16m x 16j, work-queued over 12 warps; acc 8 f =====
        for (int t = wid; t < 32; t += NW) {
            const int mt = t >> 2, jt = t & 3;
            float acc[2][4];
#pragma unroll
            for (int a = 0; a < 2; a++)
#pragma unroll
                for (int e = 0; e < 4; e++) acc[a][e] = 0.f;
            for (int t3 = 0; t3 < 3; t3++) {
                const uint4* wb = (t3 == 2) ? g_wf_lo : g_wf_hi;
                uint32_t Bb = sb + cur + ((t3 == 1) ? HL_X : 0) + bOffX +
                              jt * 16 * STB_X;
#pragma unroll
                for (int kt = 0; kt < 8; kt++) {
                    uint4 af = wb[((mt * 8 + kt) << 5) + lane];
                    uint32_t bf[4];
                    ldsm4(bf, Bb + kt * 32);
                    mma_bf16(acc[0], reinterpret_cast<uint32_t*>(&af), bf[0], bf[1]);
                    mma_bf16(acc[1], reinterpret_cast<uint32_t*>(&af), bf[2], bf[3]);
                }
            }
#pragma unroll
            for (int nt = 0; nt < 2; nt++) {
                int d0 = mt * 16 + r_, j = jt * 16 + nt * 8 + c2;
                char* p = smem + OFF_SWT + d0 * STB_W + j * 2;
                st_split_pair(p, p + HL_SWT, acc[nt][0], acc[nt][1]);
                p += 8 * STB_W;
                st_split_pair(p, p + HL_SWT, acc[nt][2], acc[nt][3]);
            }
        }
        __syncthreads();
        // ===== G2: AM[i][d] = sum_j attn[i][j]*SWT[d][j] + msgb (M=64,N=128,K=64)
        //       32 tiles of 16i x 16d; acc 8 f =====
        for (int t = wid; t < 32; t += NW) {
            const int it2 = t & 3, dt = t >> 2;
            const int i0 = it2 * 16, d0 = dt * 16;
            float acc[2][4];
#pragma unroll
            for (int a = 0; a < 2; a++)
#pragma unroll
                for (int e = 0; e < 4; e++) acc[a][e] = 0.f;
            for (int t3 = 0; t3 < 3; t3++) {
                uint32_t Ab = sb + OFF_ATT + ((t3 == 2) ? HL_ATT : 0) + aOffW +
                              i0 * STB_W;
                uint32_t Bb = sb + OFF_SWT + ((t3 == 1) ? HL_SWT : 0) + bOffW +
                              d0 * STB_W;
#pragma unroll
                for (int kt = 0; kt < 4; kt++) {
                    uint32_t af[4], bf[4];
                    ldsm4(af, Ab + kt * 32);
                    ldsm4(bf, Bb + kt * 32);
                    mma_bf16(acc[0], af, bf[0], bf[1]);
                    mma_bf16(acc[1], af, bf[2], bf[3]);
                }
            }
#pragma unroll
            for (int nt = 0; nt < 2; nt++) {
                int d = d0 + nt * 8 + c2;
                float m0 = msgb[d], m1 = msgb[d + 1];
                char* p = smem + OFF_AM + (i0 + r_) * STB_X + d * 2;
                st_split_pair(p, p + HL_X, acc[nt][0] + m0, acc[nt][1] + m1);
                p += 8 * STB_X;
                st_split_pair(p, p + HL_X, acc[nt][2] + m0, acc[nt][3] + m1);
            }
        }
        __syncthreads();
        // ===== gates: D[g][i]; 32 tiles of 16g x 16i; acc 32 f.
        //       Reads AM + S_cur, writes S_nxt -> no internal barriers. =====
        for (int t = wid; t < 32; t += NW) {
            const int gt = t >> 2, ic = t & 3;
            float acc[4][2][4];   // set(r,z,in,hn) x n x elem = 32 floats
#pragma unroll
            for (int s = 0; s < 4; s++)
#pragma unroll
                for (int n = 0; n < 2; n++)
#pragma unroll
                    for (int e = 0; e < 4; e++) acc[s][n][e] = 0.f;
#pragma unroll
            for (int src = 0; src < 2; src++) {
                const uint32_t Bbase = (src == 0) ? (uint32_t)OFF_AM : cur;
                for (int t3 = 0; t3 < 3; t3++) {
                    const uint4* wb = (t3 == 2) ? g_wf_lo : g_wf_hi;
                    uint32_t Bb = sb + Bbase + ((t3 == 1) ? HL_X : 0) + bOffX +
                                  ic * 16 * STB_X;
#pragma unroll
                    for (int kt = 0; kt < 8; kt++) {
                        uint32_t bf[4];
                        ldsm4(bf, Bb + kt * 32);
#pragma unroll
                        for (int gate = 0; gate < 3; gate++) {
                            const int set = (gate < 2) ? gate : (2 + src);
                            const int tile = 1 + gate + 3 * src;
                            uint4 af = wb[((tile * 64 + gt * 8 + kt) << 5) + lane];
                            mma_bf16(acc[set][0], reinterpret_cast<uint32_t*>(&af),
                                     bf[0], bf[1]);
                            mma_bf16(acc[set][1], reinterpret_cast<uint32_t*>(&af),
                                     bf[2], bf[3]);
                        }
                    }
                }
            }
            // GRU pointwise for this 16g x 16i tile; write S_nxt
#pragma unroll
            for (int q = 0; q < 2; q++) {
                int g = gt * 16 + r_ + q * 8;
                float bR = vbr[g], bZ = vbz[g], bI = vbin[g], bH = vbhn[g];
#pragma unroll
                for (int n = 0; n < 2; n++) {
#pragma unroll
                    for (int e = 0; e < 2; e++) {
                        int i = ic * 16 + n * 8 + c2 + e;
                        int ci = q * 2 + e;
                        float R  = sigmoidf_(acc[0][n][ci] + bR);
                        float Z  = sigmoidf_(acc[1][n][ci] + bZ);
                        float Nv = tanhf(acc[2][n][ci] + bI +
                                         R * (acc[3][n][ci] + bH));
                        char* so = smem + cur + i * STB_X + g * 2;
                        float sold = rbf(so) + rbf(so + HL_X);
                        float hres = *reinterpret_cast<float*>(
                            smem + OFF_H + (i * 128 + g) * 4);
                        float sv = (1.f - Z) * Nv + Z * sold + hres;
                        char* sn = smem + nxt + i * STB_X + g * 2;
                        __nv_bfloat16 hh = __float2bfloat16(sv);
                        *reinterpret_cast<__nv_bfloat16*>(sn) = hh;
                        *reinterpret_cast<__nv_bfloat16*>(sn + HL_X) =
                            __float2bfloat16(sv - __bfloat162float(hh));
                    }
                }
            }
        }
        __syncthreads();
        { uint32_t tsw = cur; cur = nxt; nxt = tsw; }
    }

    // ===== readout (S in `cur`) =====
    if (tid < 64) {
        float acc = 0.f;
#pragma unroll 8
        for (int k = 0; k < 128; k++) {
            char* sp = smem + cur + tid * STB_X + k * 2;
            acc += (rbf(sp) + rbf(sp + HL_X)) * mlp2_w[k];
        }
        scr[tid] = acc + mlp2_b[0];
    }
    __syncthreads();
    if (tid < 128) {
        float acc = 0.f;
#pragma unroll 4
        for (int n = 0; n < 64; n++) {
            char* sp = smem + cur + n * STB_X + tid * 2;
            acc += scr[n] * (rbf(sp) + rbf(sp + HL_X));
        }
        scr[64 + tid] = acc;
    }
    __syncthreads();
    if (tid < 64) {
        float acc = 0.f;
#pragma unroll 4
        for (int d = 0; d < 128; d++) acc += scr[64 + d] * mlp1_w[d * 64 + tid];
        float ws = 0.f;
#pragma unroll
        for (int n = 0; n < 64; n++) ws += scr[n];
        out[(size_t)b * 64 + tid] = acc + ws * mlp1_b[tid];
    }
}

extern "C" void kernel_launch(void* const* d_in, const int* in_sizes, int n_in,
                              void* d_out, int out_size) {
    const float* h      = (const float*)d_in[0];
    // d_in[1] = adj: unused by the math (shape only)
    const float* a_src  = (const float*)d_in[2];
    const float* a_dst  = (const float*)d_in[3];
    const float* w      = (const float*)d_in[4];
    const float* bias   = (const float*)d_in[5];
    const float* W_ih   = (const float*)d_in[6];
    const float* W_hh   = (const float*)d_in[7];
    const float* b_ih   = (const float*)d_in[8];
    const float* b_hh   = (const float*)d_in[9];
    const float* mlp1_w = (const float*)d_in[10];
    const float* mlp1_b = (const float*)d_in[11];
    const float* mlp2_w = (const float*)d_in[12];
    const float* mlp2_b = (const float*)d_in[13];
    const int*   steps  = (n_in > 14) ? (const int*)d_in[14] : nullptr;

    int batches = in_sizes[0] / (64 * 128);

    cudaFuncSetAttribute(fignn_mma, cudaFuncAttributeMaxDynamicSharedMemorySize,
                         SMEM_TOTAL);
    prep_weights<<<(7 * 64 * 32 + 255) / 256, 256>>>(w, W_ih, W_hh);
    fignn_mma<<<batches, THR, SMEM_TOTAL>>>(h, a_src, a_dst, bias, b_ih, b_hh,
                                            mlp1_w, mlp1_b, mlp2_w, mlp2_b,
                                            steps, (float*)d_out);
}